// round 15
// baseline (speedup 1.0000x reference)
#include <cuda_runtime.h>
#include <cuda_fp16.h>
#include <stdint.h>

#define BATCH 16
#define CIN   256
#define COUT  256
#define HW    1024
#define NE    8
#define NCHUNK 36             /* 9 taps * 4 ci-quarters of 64 */
#define STAGE  32768          /* A 16KB + B 16KB */
#define NSTAGE 3
#define SMEM_TOTAL (NSTAGE * STAGE + 1024)

__device__ __forceinline__ uint32_t smem_u32(const void* p) {
    uint32_t a;
    asm("{ .reg .u64 t; cvta.to.shared.u64 t, %1; cvt.u32.u64 %0, t; }" : "=r"(a) : "l"(p));
    return a;
}
#define SWZ(off) ((off) ^ (((off) >> 3) & 0x70))

#define CP_ASYNC16(dst, src) \
    asm volatile("cp.async.cg.shared.global [%0], [%1], 16;" :: "r"(dst), "l"(src) : "memory")
#define CP_COMMIT() asm volatile("cp.async.commit_group;" ::: "memory")
#define CP_WAIT1()  asm volatile("cp.async.wait_group 1;" ::: "memory")

#define LDSM_X4(r, addr) \
    asm volatile("ldmatrix.sync.aligned.m8n8.x4.shared.b16 {%0,%1,%2,%3}, [%4];" \
        : "=r"((r)[0]), "=r"((r)[1]), "=r"((r)[2]), "=r"((r)[3]) : "r"(addr))

#define MMA16816(d, a, b0, b1) \
    asm volatile("mma.sync.aligned.m16n8k16.row.col.f32.f16.f16.f32 " \
        "{%0,%1,%2,%3}, {%4,%5,%6,%7}, {%8,%9}, {%0,%1,%2,%3};" \
        : "+f"((d)[0]), "+f"((d)[1]), "+f"((d)[2]), "+f"((d)[3]) \
        : "r"((a)[0]), "r"((a)[1]), "r"((a)[2]), "r"((a)[3]), "r"(b0), "r"(b1))

__device__ int g_decisions[BATCH];
__device__ float g_pooled[BATCH * CIN];
// weights, tap-major fp16 pairs: [e][t][co][ci/2] u32
__device__ __align__(256) uint32_t g_wh[(size_t)NE * 9 * COUT * 128];            // 9.4 MB
// padded+shifted X, pixel-major fp16 pairs: [i][dx 3][34 y][32 px][128 ci-pairs]
__device__ __align__(256) uint32_t g_xq[(size_t)BATCH * 3 * 34 * 32 * 128];      // 26.7 MB

__device__ __forceinline__ uint32_t pack2(float v0, float v1) {
    __half h0 = __float2half_rn(v0), h1 = __float2half_rn(v1);
    return ((uint32_t)__half_as_ushort(h1) << 16) | __half_as_ushort(h0);
}

// ---------------- kernel 1: fused prep (R10-proven) ----------------
// blocks [0,544): (i = b/34, y = b%34) -> g_xq rows + pooling partial
// blocks [544, 544+2048): weight row (e*256+co) -> [e][t][co][ci]
__global__ void prep_kernel(const float* __restrict__ x, const float* __restrict__ we) {
    __shared__ float sX[32 * 257];               // [px][ci] padded
    const int b = blockIdx.x, tid = threadIdx.x;
    if (b < 544) {
        const int i = b / 34, y = b % 34;        // g_xq row y holds image row y-1
        const bool valid = (y >= 1 && y <= 32);
        if (valid) {
            const float* src = x + (size_t)i * CIN * HW + (size_t)(y - 1) * 32;
            for (int idx = tid; idx < 8192; idx += 256) {
                int ci = idx >> 5, px = idx & 31;
                sX[px * 257 + ci] = src[(size_t)ci * HW + px];
            }
        }
        __syncthreads();
        if (valid) {
            float s = 0.f;
            #pragma unroll 8
            for (int px = 0; px < 32; px++) s += sX[px * 257 + tid];
            atomicAdd(&g_pooled[i * CIN + tid], s * (1.0f / HW));
        }
        uint32_t* dst = g_xq + (((size_t)i * 3) * 34 + y) * 32 * 128;
        for (int idx = tid; idx < 3 * 32 * 128; idx += 256) {
            int cp = idx & 127;
            int px = (idx >> 7) & 31;
            int dx = idx >> 12;
            float v0 = 0.f, v1 = 0.f;
            int sxp = px + dx - 1;
            if (valid && (unsigned)sxp < 32u) {
                v0 = sX[sxp * 257 + 2 * cp];
                v1 = sX[sxp * 257 + 2 * cp + 1];
            }
            dst[((size_t)dx * 34 * 32 + px) * 128 + cp] = pack2(v0, v1);
        }
    } else {
        __shared__ float sW[2304];
        const int row = b - 544;                  // e*256+co
        const int e = row >> 8, co = row & 255;
        const float* src = we + (size_t)row * 2304;
        for (int k = tid; k < 2304; k += 256) sW[k] = src[k];
        __syncthreads();
        for (int idx = tid; idx < 9 * 128; idx += 256) {
            int t = idx >> 7, cip = idx & 127;
            int ci0 = cip * 2;
            g_wh[((size_t)(e * 9 + t) * COUT + co) * 128 + cip] =
                pack2(sW[ci0 * 9 + t], sW[(ci0 + 1) * 9 + t]);
        }
    }
}

// ---------------- kernel 2: router finish ----------------
__global__ void router_finish_kernel(const float* __restrict__ wc,
                                     const float* __restrict__ bc) {
    __shared__ float sLog[BATCH][NE];
    const int tid = threadIdx.x;
    const int b = tid >> 3, e = tid & 7;
    const float* p = g_pooled + b * CIN;
    const float* w = wc + e * CIN;
    float sum = 0.f;
    #pragma unroll 8
    for (int k = 0; k < CIN; k++) sum += p[k] * w[k];
    sLog[b][e] = sum + bc[e];
    __syncthreads();
    if (tid < BATCH) {
        float best = sLog[tid][0]; int bi = 0;
        #pragma unroll
        for (int ee = 1; ee < NE; ee++)
            if (sLog[tid][ee] > best) { best = sLog[tid][ee]; bi = ee; }
        g_decisions[tid] = bi;
    }
}

// ---------------- kernel 3: HMMA implicit GEMM (R8 schedule, non-trans B) ---
// CTA tile 128co x 128px; 4 warps (2co x 2px) of 64x64. K-chunk 64, 3-stage.
// B smem [128 px][64 ci = 128B] SW128; B frags via NON-trans ldmatrix.
// grid (8 px-tiles of 128, 2 co-tiles of 128, 128 pairs), 128 threads, 2 CTA/SM.
__global__ void __launch_bounds__(128, 2)
gemm_kernel(const float* __restrict__ be, float* __restrict__ out) {
    extern __shared__ __align__(16) char dynraw[];
    char* dyn = (char*)(((uintptr_t)dynraw + 1023) & ~(uintptr_t)1023);
    const uint32_t dynu = smem_u32(dyn);

    __shared__ int sDec[BATCH];
    const int tid = threadIdx.x;
    const int ntile = blockIdx.x, mtile = blockIdx.y, pair = blockIdx.z;
    const int i = pair & 15, e = pair >> 4;

    if (tid < BATCH) sDec[tid] = g_decisions[tid];
    __syncthreads();
    bool need = false;
    #pragma unroll
    for (int j = 0; j < BATCH; j++) need |= (sDec[j] == e);
    if (!need) return;

    const int lane = tid & 31, wid = tid >> 5;
    const int wm = wid & 1, wn = wid >> 1;     // 2x2 warp grid, 64co x 64px each
    const int y0 = ntile << 2;                 // first image row of 128-px tile

    float acc[4][8][4];
    #pragma unroll
    for (int ma = 0; ma < 4; ma++)
        #pragma unroll
        for (int na = 0; na < 8; na++)
            #pragma unroll
            for (int c = 0; c < 4; c++) acc[ma][na][c] = 0.f;

    // A fragments: rows = co (SW128, R8-identical)
    const uint32_t aFragBase = (uint32_t)((wm * 64 + (lane & 15)) * 128 + ((lane >> 4) << 4));
    // B fragments: rows = px, NON-trans (R12-validated pairing)
    uint32_t bFragBase[4];
    #pragma unroll
    for (int pb = 0; pb < 4; pb++)
        bFragBase[pb] = (uint32_t)((wn * 64 + pb * 16 + (lane & 7) + ((lane >> 4) << 3)) * 128
                                   + (((lane >> 3) & 1) << 4));

    // gmem->smem maps (128 threads)
    const int ldcA = tid & 7;                   // A: 8 x 16B per 128B row
    const int coL0 = tid >> 3;                  // rows 0..15, +16 per round (8 rounds)
    // B: 128 px-rows x 128B; thread = one row, 8 x 16B
    const uint32_t stsB = (uint32_t)(tid * 128);

    auto load_stage = [&](int buf, int it) {
        const int t = it >> 2, qc = it & 3;
        const int ty = t / 3, tx = t % 3;
        const uint32_t st = dynu + buf * STAGE;
        // A: [128 co][64 ci = 128B]
        const uint32_t* wrow = g_wh + ((size_t)(e * 9 + t) * COUT + (mtile << 7) + coL0) * 128
                               + (qc << 5) + ldcA * 4;
        #pragma unroll
        for (int r = 0; r < 8; r++)
            CP_ASYNC16(st + SWZ((coL0 + r * 16) * 128 + ldcA * 16),
                       (const char*)(wrow + (size_t)r * 16 * 128));
        // B: [128 px][64 ci = 128B]; px rows are 512B-strided, qc selects 128B
        const char* xbase = (const char*)g_xq
            + ((((size_t)(i * 3 + tx) * 34 + y0 + ty) * 32) << 9)   // *512B
            + (qc << 7) + (size_t)tid * 512;
        #pragma unroll
        for (int c = 0; c < 8; c++)
            CP_ASYNC16(st + 16384 + SWZ(stsB + c * 16), xbase + c * 16);
    };

    load_stage(0, 0); CP_COMMIT();
    load_stage(1, 1); CP_COMMIT();

    int buf = 0, pfbuf = 2;
    #pragma unroll 1
    for (int it = 0; it < NCHUNK; ++it) {
        CP_WAIT1();
        __syncthreads();
        if (it + 2 < NCHUNK) { load_stage(pfbuf, it + 2); CP_COMMIT(); }

        const uint32_t bA = dynu + buf * STAGE;
        const uint32_t bB = bA + 16384;
        #pragma unroll
        for (int s = 0; s < 4; s++) {
            uint32_t af[4][4], bf[4][4];
            #pragma unroll
            for (int ma = 0; ma < 4; ma++)
                LDSM_X4(af[ma], bA + SWZ(aFragBase + ma * 2048 + s * 32));
            #pragma unroll
            for (int pb = 0; pb < 4; pb++)
                LDSM_X4(bf[pb], bB + SWZ(bFragBase[pb] + s * 32));
            #pragma unroll
            for (int ma = 0; ma < 4; ma++)
                #pragma unroll
                for (int pb = 0; pb < 4; pb++) {
                    MMA16816(acc[ma][pb * 2],     af[ma], bf[pb][0], bf[pb][1]);
                    MMA16816(acc[ma][pb * 2 + 1], af[ma], bf[pb][2], bf[pb][3]);
                }
        }
        buf = (buf == 2) ? 0 : buf + 1;
        pfbuf = (pfbuf == 2) ? 0 : pfbuf + 1;
    }

    // ---------------- epilogue (R8-identical mapping) ----------------
    const int coBase = (mtile << 7) + wm * 64 + (lane >> 2);
    const int pixBase = (ntile << 7) + wn * 64 + 2 * (lane & 3);
    float bias0[4], bias1[4];
    #pragma unroll
    for (int ma = 0; ma < 4; ma++) {
        bias0[ma] = be[(e << 8) + coBase + ma * 16];
        bias1[ma] = be[(e << 8) + coBase + ma * 16 + 8];
    }
    #pragma unroll 1
    for (int j = 0; j < BATCH; j++) {
        if (sDec[j] != e) continue;
        float* ob = out + ((size_t)(j * BATCH + i) << 18);
        #pragma unroll
        for (int ma = 0; ma < 4; ma++) {
            const int co = coBase + ma * 16;
            #pragma unroll
            for (int na = 0; na < 8; na++) {
                const int pix = pixBase + na * 8;
                float2 v0, v1;
                v0.x = fmaxf(acc[ma][na][0] + bias0[ma], 0.f);
                v0.y = fmaxf(acc[ma][na][1] + bias0[ma], 0.f);
                v1.x = fmaxf(acc[ma][na][2] + bias1[ma], 0.f);
                v1.y = fmaxf(acc[ma][na][3] + bias1[ma], 0.f);
                *(float2*)(ob + (size_t)co * HW + pix)       = v0;
                *(float2*)(ob + (size_t)(co + 8) * HW + pix) = v1;
            }
        }
    }
}

// ---------------------------------------------------------------------------
extern "C" void kernel_launch(void* const* d_in, const int* in_sizes, int n_in,
                              void* d_out, int out_size) {
    const float* x  = (const float*)d_in[0];
    const float* wc = (const float*)d_in[1];
    const float* bc = (const float*)d_in[2];
    const float* we = (const float*)d_in[3];
    const float* be = (const float*)d_in[4];
    float* out = (float*)d_out;

    static int smemSet = 0;
    if (!smemSet) {
        cudaFuncSetAttribute(gemm_kernel, cudaFuncAttributeMaxDynamicSharedMemorySize,
                             SMEM_TOTAL);
        smemSet = 1;
    }

    void* pooledPtr = nullptr;
    cudaGetSymbolAddress(&pooledPtr, g_pooled);
    cudaMemsetAsync(pooledPtr, 0, BATCH * CIN * sizeof(float));

    prep_kernel<<<544 + NE * COUT, 256>>>(x, we);
    router_finish_kernel<<<1, 128>>>(wc, bc);
    gemm_kernel<<<dim3(8, 2, BATCH * NE), 128, SMEM_TOTAL>>>(be, out);
}

// round 16
// speedup vs baseline: 1.4339x; 1.4339x over previous
#include <cuda_runtime.h>
#include <cuda_fp16.h>
#include <stdint.h>

#define BATCH 16
#define CIN   256
#define COUT  256
#define HW    1024
#define NE    8
#define NCHUNK 36             /* 9 taps * 4 ci-quarters of 64 */
#define STAGE  32768          /* A 16KB + B 16KB */
#define NSTAGE 3
#define SMEM_TOTAL (NSTAGE * STAGE + 1024)

// ---------------- helpers ----------------
__device__ __forceinline__ uint32_t smem_u32(const void* p) {
    uint32_t a;
    asm("{ .reg .u64 t; cvta.to.shared.u64 t, %1; cvt.u32.u64 %0, t; }" : "=r"(a) : "l"(p));
    return a;
}
#define SWZ(off) ((off) ^ (((off) >> 3) & 0x70))

#define CP_ASYNC16(dst, src) \
    asm volatile("cp.async.cg.shared.global [%0], [%1], 16;" :: "r"(dst), "l"(src) : "memory")
#define CP_COMMIT() asm volatile("cp.async.commit_group;" ::: "memory")
#define CP_WAIT1()  asm volatile("cp.async.wait_group 1;" ::: "memory")

#define LDSM_X4(r, addr) \
    asm volatile("ldmatrix.sync.aligned.m8n8.x4.shared.b16 {%0,%1,%2,%3}, [%4];" \
        : "=r"((r)[0]), "=r"((r)[1]), "=r"((r)[2]), "=r"((r)[3]) : "r"(addr))
#define LDSM_X4T(r, addr) \
    asm volatile("ldmatrix.sync.aligned.m8n8.x4.trans.shared.b16 {%0,%1,%2,%3}, [%4];" \
        : "=r"((r)[0]), "=r"((r)[1]), "=r"((r)[2]), "=r"((r)[3]) : "r"(addr))

#define MMA16816(d, a, b0, b1) \
    asm volatile("mma.sync.aligned.m16n8k16.row.col.f32.f16.f16.f32 " \
        "{%0,%1,%2,%3}, {%4,%5,%6,%7}, {%8,%9}, {%0,%1,%2,%3};" \
        : "+f"((d)[0]), "+f"((d)[1]), "+f"((d)[2]), "+f"((d)[3]) \
        : "r"((a)[0]), "r"((a)[1]), "r"((a)[2]), "r"((a)[3]), "r"(b0), "r"(b1))

// ---------------- device scratch ----------------
__device__ int g_decisions[BATCH];
__device__ float g_pooled[BATCH * CIN];
// weights, tap-major fp16 pairs: [e][t][co][ci/2] u32
__device__ __align__(256) uint32_t g_wh[(size_t)NE * 9 * COUT * 128];          // 9.4 MB
// padded+shifted X fp16 pairs: [i][dx 3][ci][34 rows][16 px-pairs] u32
__device__ __align__(256) uint32_t g_xp[(size_t)BATCH * 3 * CIN * 34 * 16];    // 26.7 MB

__device__ __forceinline__ uint32_t pack2(float v0, float v1) {
    __half h0 = __float2half_rn(v0), h1 = __float2half_rn(v1);
    return ((uint32_t)__half_as_ushort(h1) << 16) | __half_as_ushort(h0);
}

// ---------------- kernel 1: fused prep (xpad + weight reorder + pooling) ----
// (R8-proven, 28.8 us)
__global__ void prep_kernel(const float* __restrict__ x, const float* __restrict__ we) {
    __shared__ float s[2304];
    __shared__ float sRed[8];
    const int b = blockIdx.x, tid = threadIdx.x;
    if (b < 4096) {
        const int i = b >> 8, ci = b & 255;
        const float* src = x + ((size_t)i * CIN + ci) * HW;
        for (int k = tid; k < 1024; k += 256) s[k] = src[k];
        __syncthreads();
        {
            float v = s[tid] + s[tid + 256] + s[tid + 512] + s[tid + 768];
            #pragma unroll
            for (int o = 16; o > 0; o >>= 1) v += __shfl_xor_sync(0xffffffffu, v, o);
            if ((tid & 31) == 0) sRed[tid >> 5] = v;
            __syncthreads();
            if (tid == 0) {
                float t = 0.f;
                #pragma unroll
                for (int w = 0; w < 8; w++) t += sRed[w];
                g_pooled[i * CIN + ci] = t * (1.0f / HW);
            }
        }
        uint32_t* dst = g_xp + (((size_t)i * 3 * CIN + ci) * 34) * 16;
        for (int idx = tid; idx < 3 * 34 * 16; idx += 256) {
            int xp = (idx & 15) * 2;
            int rest = idx >> 4;
            int yy = rest % 34;
            int dxs = rest / 34;
            float v0 = 0.f, v1 = 0.f;
            if (yy >= 1 && yy <= 32) {
                int sx0 = xp + dxs - 1;
                if ((unsigned)sx0 < 32u)       v0 = s[(yy - 1) * 32 + sx0];
                if ((unsigned)(sx0 + 1) < 32u) v1 = s[(yy - 1) * 32 + sx0 + 1];
            }
            dst[((size_t)dxs * CIN * 34 + yy) * 16 + (idx & 15)] = pack2(v0, v1);
        }
    } else {
        const int row = b - 4096;                 // e*256+co
        const int e = row >> 8, co = row & 255;
        const float* src = we + (size_t)row * 2304;
        for (int k = tid; k < 2304; k += 256) s[k] = src[k];
        __syncthreads();
        for (int idx = tid; idx < 9 * 128; idx += 256) {
            int t = idx >> 7, cip = idx & 127;
            int ci0 = cip * 2;
            g_wh[((size_t)(e * 9 + t) * COUT + co) * 128 + cip] =
                pack2(s[ci0 * 9 + t], s[(ci0 + 1) * 9 + t]);
        }
    }
}

// ---------------- kernel 2: router finish ----------------
__global__ void router_finish_kernel(const float* __restrict__ wc,
                                     const float* __restrict__ bc) {
    __shared__ float sLog[BATCH][NE];
    const int tid = threadIdx.x;
    const int b = tid >> 3, e = tid & 7;
    const float* p = g_pooled + b * CIN;
    const float* w = wc + e * CIN;
    float sum = 0.f;
    #pragma unroll 8
    for (int k = 0; k < CIN; k++) sum += p[k] * w[k];
    sLog[b][e] = sum + bc[e];
    __syncthreads();
    if (tid < BATCH) {
        float best = sLog[tid][0]; int bi = 0;
        #pragma unroll
        for (int ee = 1; ee < NE; ee++)
            if (sLog[tid][ee] > best) { best = sLog[tid][ee]; bi = ee; }
        g_decisions[tid] = bi;
    }
}

// ---------------- kernel 3: HMMA implicit GEMM (R8 + B-frag double-buffer) --
// CTA tile 128co x 128px; 4 warps of 64x64. K-chunk 64, 3-stage cp.async.
// grid (8 px-tiles of 128, 2 co-tiles of 128, 128 pairs), 128 thr, 2 CTA/SM.
__global__ void __launch_bounds__(128, 2)
gemm_kernel(const float* __restrict__ be, float* __restrict__ out) {
    extern __shared__ __align__(16) char dynraw[];
    char* dyn = (char*)(((uintptr_t)dynraw + 1023) & ~(uintptr_t)1023);
    const uint32_t dynu = smem_u32(dyn);

    __shared__ int sDec[BATCH];
    const int tid = threadIdx.x;
    const int ntile = blockIdx.x, mtile = blockIdx.y, pair = blockIdx.z;
    const int i = pair & 15, e = pair >> 4;

    if (tid < BATCH) sDec[tid] = g_decisions[tid];
    __syncthreads();
    bool need = false;
    #pragma unroll
    for (int j = 0; j < BATCH; j++) need |= (sDec[j] == e);
    if (!need) return;

    const int lane = tid & 31, wid = tid >> 5;
    const int wm = wid & 1, wn = wid >> 1;     // 2x2 warp grid, 64co x 64px each
    const int y0 = ntile << 2;                 // first image row of 128-px tile

    float acc[4][8][4];
    #pragma unroll
    for (int ma = 0; ma < 4; ma++)
        #pragma unroll
        for (int na = 0; na < 8; na++)
            #pragma unroll
            for (int c = 0; c < 4; c++) acc[ma][na][c] = 0.f;

    // A fragment base (within 16KB A region): 128B rows, SW128 swizzle
    const uint32_t aFragBase = (uint32_t)((wm * 64 + (lane & 15)) * 128 + ((lane >> 4) << 4));
    // B fragment addresses (within 16KB B region): 64 ci rows x 256B, XOR swizzle
    uint32_t bAddr[4];
    #pragma unroll
    for (int pb = 0; pb < 4; pb++) {
        uint32_t p = (uint32_t)(wn * 128 + pb * 32 + ((lane >> 4) << 4));  // px byte off
        bAddr[pb] = (uint32_t)((lane & 15) * 256) + ((((p >> 4) ^ (lane & 7)) << 4));
    }

    // gmem->smem maps (R8-identical)
    const int ldcA = tid & 7;                   // A: 8 chunks of 16B per 128B row
    const int coL0 = tid >> 3;                  // 0..15, +16 per round (8 rounds)
    const int ldcB = tid & 15;                  // B: 16 chunks of 16B per 256B row
    const int ciL0 = tid >> 4;                  // 0..7, +8 per round (8 rounds)
    const uint32_t dstB0 = (uint32_t)(((ldcB ^ ciL0) & 15) << 4);

    auto load_stage = [&](int buf, int it) {
        const int t = it >> 2, qc = it & 3;
        const int ty = t / 3, tx = t % 3;
        const uint32_t st = dynu + buf * STAGE;
        // A: [128 co][64 ci = 128B]
        const uint32_t* wrow = g_wh + ((size_t)(e * 9 + t) * COUT + (mtile << 7) + coL0) * 128
                               + (qc << 5) + ldcA * 4;
        #pragma unroll
        for (int r = 0; r < 8; r++)
            CP_ASYNC16(st + SWZ((coL0 + r * 16) * 128 + ldcA * 16),
                       (const char*)(wrow + (size_t)r * 16 * 128));
        // B: [64 ci][256B = 128px over 4 image rows], contiguous per ci
        const size_t bRow64 = ((size_t)(i * 3 + tx) * CIN + (qc << 6) + ciL0) * 34 + y0 + ty;
        #pragma unroll
        for (int r = 0; r < 8; r++) {
            const int ci = ciL0 + r * 8;
            CP_ASYNC16(st + 16384 + ci * 256 + dstB0,
                       (const char*)g_xp + ((bRow64 + (size_t)r * 8 * 34) << 6) + ldcB * 16);
        }
    };

    load_stage(0, 0); CP_COMMIT();
    load_stage(1, 1); CP_COMMIT();

    int buf = 0, pfbuf = 2;
    #pragma unroll 1
    for (int it = 0; it < NCHUNK; ++it) {
        CP_WAIT1();
        __syncthreads();
        if (it + 2 < NCHUNK) { load_stage(pfbuf, it + 2); CP_COMMIT(); }

        const uint32_t bA = dynu + buf * STAGE;
        const uint32_t bB = bA + 16384;

        // ---- B-fragment double-buffer across s-steps ----
        uint32_t bf[2][4][4];
        #pragma unroll
        for (int pb = 0; pb < 4; pb++)
            LDSM_X4T(bf[0][pb], bB + 0 * 4096 + bAddr[pb]);

        #pragma unroll
        for (int s = 0; s < 4; s++) {
            const int cur = s & 1, nxt = cur ^ 1;
            if (s < 3) {
                #pragma unroll
                for (int pb = 0; pb < 4; pb++)
                    LDSM_X4T(bf[nxt][pb], bB + (s + 1) * 4096 + bAddr[pb]);
            }
            uint32_t af[4][4];
            #pragma unroll
            for (int ma = 0; ma < 4; ma++)
                LDSM_X4(af[ma], bA + SWZ(aFragBase + ma * 2048 + s * 32));
            #pragma unroll
            for (int ma = 0; ma < 4; ma++)
                #pragma unroll
                for (int pb = 0; pb < 4; pb++) {
                    MMA16816(acc[ma][pb * 2],     af[ma], bf[cur][pb][0], bf[cur][pb][1]);
                    MMA16816(acc[ma][pb * 2 + 1], af[ma], bf[cur][pb][2], bf[cur][pb][3]);
                }
        }
        buf = (buf == 2) ? 0 : buf + 1;
        pfbuf = (pfbuf == 2) ? 0 : pfbuf + 1;
    }

    // ---------------- epilogue (R8-identical) ----------------
    const int coBase = (mtile << 7) + wm * 64 + (lane >> 2);
    const int pixBase = (ntile << 7) + wn * 64 + 2 * (lane & 3);
    float bias0[4], bias1[4];
    #pragma unroll
    for (int ma = 0; ma < 4; ma++) {
        bias0[ma] = be[(e << 8) + coBase + ma * 16];
        bias1[ma] = be[(e << 8) + coBase + ma * 16 + 8];
    }
    #pragma unroll 1
    for (int j = 0; j < BATCH; j++) {
        if (sDec[j] != e) continue;
        float* ob = out + ((size_t)(j * BATCH + i) << 18);
        #pragma unroll
        for (int ma = 0; ma < 4; ma++) {
            const int co = coBase + ma * 16;
            #pragma unroll
            for (int na = 0; na < 8; na++) {
                const int pix = pixBase + na * 8;
                float2 v0, v1;
                v0.x = fmaxf(acc[ma][na][0] + bias0[ma], 0.f);
                v0.y = fmaxf(acc[ma][na][1] + bias0[ma], 0.f);
                v1.x = fmaxf(acc[ma][na][2] + bias1[ma], 0.f);
                v1.y = fmaxf(acc[ma][na][3] + bias1[ma], 0.f);
                *(float2*)(ob + (size_t)co * HW + pix)       = v0;
                *(float2*)(ob + (size_t)(co + 8) * HW + pix) = v1;
            }
        }
    }
}

// ---------------------------------------------------------------------------
extern "C" void kernel_launch(void* const* d_in, const int* in_sizes, int n_in,
                              void* d_out, int out_size) {
    const float* x  = (const float*)d_in[0];
    const float* wc = (const float*)d_in[1];
    const float* bc = (const float*)d_in[2];
    const float* we = (const float*)d_in[3];
    const float* be = (const float*)d_in[4];
    float* out = (float*)d_out;

    static int smemSet = 0;
    if (!smemSet) {
        cudaFuncSetAttribute(gemm_kernel, cudaFuncAttributeMaxDynamicSharedMemorySize,
                             SMEM_TOTAL);
        smemSet = 1;
    }

    prep_kernel<<<4096 + NE * COUT, 256>>>(x, we);
    router_finish_kernel<<<1, 128>>>(wc, bc);
    gemm_kernel<<<dim3(8, 2, BATCH * NE), 128, SMEM_TOTAL>>>(be, out);
}